// round 12
// baseline (speedup 1.0000x reference)
#include <cuda_runtime.h>
#include <cstdint>

// Shapes (fixed for this problem)
#define B_   64
#define N_   2048
#define A_   512
#define RNN_ 1024
#define DW_  1024
#define DS_  1024

// Scratch (device globals: no allocation allowed)
__device__ float g_hword[B_ * A_];              // 128 KB
__device__ float g_scores[B_ * N_];             // 512 KB (raw scores)
__device__ float g_stats[2 * B_];               // [b]=max, [B_+b]=1/sum

__device__ __forceinline__ float tanh_fast(float x) {
    float r;
    asm("tanh.approx.f32 %0, %1;" : "=f"(r) : "f"(x));
    return r;
}

__device__ __forceinline__ float warp_sum(float v) {
    #pragma unroll
    for (int o = 16; o; o >>= 1) v += __shfl_xor_sync(0xffffffffu, v, o);
    return v;
}

// ---------------------------------------------------------------------------
// K1 (fused GEMM + bias): hw[b][a] = bias[a] + h[b,:] . W[a,:]
// grid = (A_/32 = 16, B_/16 = 4), block = 256. K chunked x64 through smem.
// Each thread owns (one b, two a's). Single node replaces k1_gemm + k1_reduce.
// ---------------------------------------------------------------------------
__global__ void k1_fused(const float* __restrict__ h,
                         const float* __restrict__ W,
                         const float* __restrict__ bias,
                         float* __restrict__ hw) {
    const int a0 = blockIdx.x * 32;
    const int b0 = blockIdx.y * 16;

    __shared__ float sH[16][64 + 4];
    __shared__ float sW[32][64 + 4];

    const int b  = threadIdx.x & 15;       // 0..15
    const int ag = threadIdx.x >> 4;       // 0..15, owns a's {2*ag, 2*ag+1}

    float acc0 = 0.f, acc1 = 0.f;

    for (int k0 = 0; k0 < RNN_; k0 += 64) {
        // stage h tile: 16 rows x 16 float4 = 256 loads (1/thread)
        {
            const int row = threadIdx.x >> 4, kk = threadIdx.x & 15;
            float4 v = *(const float4*)(h + (size_t)(b0 + row) * RNN_ + k0 + kk * 4);
            *(float4*)(&sH[row][kk * 4]) = v;
        }
        // stage W tile: 32 rows x 16 float4 = 512 loads (2/thread)
        #pragma unroll
        for (int i = 0; i < 2; i++) {
            const int idx = threadIdx.x + i * 256;
            const int row = idx >> 4, kk = idx & 15;
            float4 v = *(const float4*)(W + (size_t)(a0 + row) * RNN_ + k0 + kk * 4);
            *(float4*)(&sW[row][kk * 4]) = v;
        }
        __syncthreads();

        #pragma unroll 16
        for (int k4 = 0; k4 < 16; k4++) {
            const float4 hv = *(const float4*)(&sH[b][k4 * 4]);
            const float4 w0 = *(const float4*)(&sW[ag * 2][k4 * 4]);
            const float4 w1 = *(const float4*)(&sW[ag * 2 + 1][k4 * 4]);
            acc0 += hv.x * w0.x + hv.y * w0.y + hv.z * w0.z + hv.w * w0.w;
            acc1 += hv.x * w1.x + hv.y * w1.y + hv.z * w1.z + hv.w * w1.w;
        }
        __syncthreads();
    }

    float* dst = hw + (size_t)(b0 + b) * A_ + a0 + ag * 2;
    dst[0] = acc0 + bias[a0 + ag * 2];
    dst[1] = acc1 + bias[a0 + ag * 2 + 1];
}

// ---------------------------------------------------------------------------
// K2: scores[b,n] = sum_a tanh(p[b,n,a] + hw[b,a]) * walpha[a]
// grid = (N_/32, B_), block = 256.  EXACT R3/R10-measured body — DO NOT TOUCH.
// ---------------------------------------------------------------------------
__global__ void k2_scores(const float* __restrict__ p,
                          const float* __restrict__ hw,
                          const float* __restrict__ walpha,
                          float* __restrict__ scores) {
    const int b = blockIdx.y;
    const int warp = threadIdx.x >> 5, lane = threadIdx.x & 31;
    const int n0 = blockIdx.x * 32 + warp * 4;

    float4 hv[4], wv[4];
    #pragma unroll
    for (int i = 0; i < 4; i++) {
        hv[i] = __ldg((const float4*)(hw + (size_t)b * A_) + lane + 32 * i);
        wv[i] = __ldg((const float4*)walpha + lane + 32 * i);
    }

    #pragma unroll
    for (int nn = 0; nn < 4; nn++) {
        const float4* pr = (const float4*)(p + ((size_t)b * N_ + n0 + nn) * A_);
        float4 v0 = __ldcs(pr + lane);
        float4 v1 = __ldcs(pr + lane + 32);
        float4 v2 = __ldcs(pr + lane + 64);
        float4 v3 = __ldcs(pr + lane + 96);

        float acc;
        acc  = tanh_fast(v0.x + hv[0].x) * wv[0].x;
        acc += tanh_fast(v0.y + hv[0].y) * wv[0].y;
        acc += tanh_fast(v0.z + hv[0].z) * wv[0].z;
        acc += tanh_fast(v0.w + hv[0].w) * wv[0].w;
        acc += tanh_fast(v1.x + hv[1].x) * wv[1].x;
        acc += tanh_fast(v1.y + hv[1].y) * wv[1].y;
        acc += tanh_fast(v1.z + hv[1].z) * wv[1].z;
        acc += tanh_fast(v1.w + hv[1].w) * wv[1].w;
        acc += tanh_fast(v2.x + hv[2].x) * wv[2].x;
        acc += tanh_fast(v2.y + hv[2].y) * wv[2].y;
        acc += tanh_fast(v2.z + hv[2].z) * wv[2].z;
        acc += tanh_fast(v2.w + hv[2].w) * wv[2].w;
        acc += tanh_fast(v3.x + hv[3].x) * wv[3].x;
        acc += tanh_fast(v3.y + hv[3].y) * wv[3].y;
        acc += tanh_fast(v3.z + hv[3].z) * wv[3].z;
        acc += tanh_fast(v3.w + hv[3].w) * wv[3].w;

        acc = warp_sum(acc);
        if (lane == 0) scores[(size_t)b * N_ + n0 + nn] = acc;
    }
}

// ---------------------------------------------------------------------------
// K3: stats-only softmax: stats[b]=max, stats[B_+b]=1/sum(exp(s-m)).
// grid = B_, block = 256.  (R10-measured, unchanged)
// ---------------------------------------------------------------------------
__global__ void k3_stats(const float* __restrict__ scores,
                         float* __restrict__ stats) {
    const int b = blockIdx.x;
    const int t = threadIdx.x;
    const int warp = t >> 5, lane = t & 31;
    __shared__ float red[8];

    const float* srow = scores + (size_t)b * N_;
    const float4 s0 = __ldg((const float4*)srow + 2 * t);
    const float4 s1 = __ldg((const float4*)srow + 2 * t + 1);

    float m = fmaxf(fmaxf(fmaxf(s0.x, s0.y), fmaxf(s0.z, s0.w)),
                    fmaxf(fmaxf(s1.x, s1.y), fmaxf(s1.z, s1.w)));
    #pragma unroll
    for (int o = 16; o; o >>= 1) m = fmaxf(m, __shfl_xor_sync(0xffffffffu, m, o));
    if (lane == 0) red[warp] = m;
    __syncthreads();
    float mm = red[0];
    #pragma unroll
    for (int j = 1; j < 8; j++) mm = fmaxf(mm, red[j]);
    __syncthreads();

    float sum = __expf(s0.x - mm) + __expf(s0.y - mm) +
                __expf(s0.z - mm) + __expf(s0.w - mm) +
                __expf(s1.x - mm) + __expf(s1.y - mm) +
                __expf(s1.z - mm) + __expf(s1.w - mm);
    sum = warp_sum(sum);
    if (lane == 0) red[warp] = sum;
    __syncthreads();
    if (t == 0) {
        float tot = red[0];
        #pragma unroll
        for (int j = 1; j < 8; j++) tot += red[j];
        stats[b] = mm;
        stats[B_ + b] = 1.0f / tot;
    }
}

// ---------------------------------------------------------------------------
// K4 (direct-output, d-split): grid = (17, B_), block = 256.
//   bx in [0,16): CTA owns d-slice [bx*64, bx*64+64) of word_res[b], streaming
//                 ALL N rows of swf; per-CTA smem partial tree (fixed order);
//                 writes out[b, DS_+slice] directly. No partial buffer, no k5.
//   bx == 16:     copies senti_feats[b] into out[b, 0:DS_).
// Prologue: whole weight row from scores+stats (8 exps/thread, 1 sync).
// ---------------------------------------------------------------------------
__global__ void __launch_bounds__(256, 8)
k4_direct(const float* __restrict__ swf,
          const float* __restrict__ scores,
          const float* __restrict__ stats,
          const float* __restrict__ senti,
          float* __restrict__ out) {
    const int b = blockIdx.y;
    const int bx = blockIdx.x;
    const int t = threadIdx.x;

    if (bx == 16) {   // senti copy CTA: 256 float4 = full DS_ row
        ((float4*)(out + (size_t)b * (DS_ + DW_)))[t] =
            __ldg((const float4*)(senti + (size_t)b * DS_) + t);
        return;
    }

    __shared__ float  sw[N_];        // 8 KB: full weight row
    __shared__ float4 sred[256];     // 4 KB: partial reduce

    {
        const float m   = __ldg(stats + b);
        const float inv = __ldg(stats + B_ + b);
        const float4* srow = (const float4*)(scores + (size_t)b * N_);
        float4 s0 = __ldg(srow + 2 * t);
        float4 s1 = __ldg(srow + 2 * t + 1);
        float4 w0, w1;
        w0.x = __expf(s0.x - m) * inv; w0.y = __expf(s0.y - m) * inv;
        w0.z = __expf(s0.z - m) * inv; w0.w = __expf(s0.w - m) * inv;
        w1.x = __expf(s1.x - m) * inv; w1.y = __expf(s1.y - m) * inv;
        w1.z = __expf(s1.z - m) * inv; w1.w = __expf(s1.w - m) * inv;
        ((float4*)sw)[2 * t]     = w0;
        ((float4*)sw)[2 * t + 1] = w1;
    }
    __syncthreads();

    const int r = t >> 4;    // 0..15 (row within 16-row group)
    const int c = t & 15;    // 0..15 (f4 column within 64-float slice)

    const float4* x = (const float4*)swf
                    + (size_t)b * (N_ * (DW_ / 4))
                    + (size_t)r * (DW_ / 4)
                    + bx * 16 + c;

    float4 acc = make_float4(0.f, 0.f, 0.f, 0.f);
    #pragma unroll 8
    for (int n = 0; n < N_ / 16; n++) {          // 128 iters, 16 rows apart
        const float wn = sw[n * 16 + r];
        const float4 v = __ldcs(x);
        acc.x += wn * v.x; acc.y += wn * v.y;
        acc.z += wn * v.z; acc.w += wn * v.w;
        x += 16 * (DW_ / 4);
    }

    sred[t] = acc;
    __syncthreads();
    #pragma unroll
    for (int s = 8; s >= 1; s >>= 1) {           // fixed-tree over r groups
        if (r < s) {
            float4 a2 = sred[t];
            const float4 b2 = sred[(r + s) * 16 + c];
            a2.x += b2.x; a2.y += b2.y; a2.z += b2.z; a2.w += b2.w;
            sred[t] = a2;
        }
        __syncthreads();
    }
    if (r == 0)
        ((float4*)(out + (size_t)b * (DS_ + DW_) + DS_))[bx * 16 + c] = sred[c];
}

// ---------------------------------------------------------------------------
extern "C" void kernel_launch(void* const* d_in, const int* in_sizes, int n_in,
                              void* d_out, int out_size) {
    const float* h      = (const float*)d_in[0];  // [B, RNN]
    const float* senti  = (const float*)d_in[1];  // [B, DS]
    const float* swf    = (const float*)d_in[2];  // [B, N, DW]
    const float* p      = (const float*)d_in[3];  // [B, N, A]
    const float* W      = (const float*)d_in[4];  // [A, RNN]
    const float* bvec   = (const float*)d_in[5];  // [A]
    const float* walpha = (const float*)d_in[6];  // [A]
    // d_in[7] = b_alpha: softmax-invariant, ignored.

    float* hw;      cudaGetSymbolAddress((void**)&hw,      g_hword);
    float* scores;  cudaGetSymbolAddress((void**)&scores,  g_scores);
    float* stats;   cudaGetSymbolAddress((void**)&stats,   g_stats);

    k1_fused <<<dim3(A_ / 32, B_ / 16), 256>>>(h, W, bvec, hw);
    k2_scores<<<dim3(N_ / 32, B_), 256>>>(p, hw, walpha, scores);
    k3_stats <<<B_, 256>>>(scores, stats);
    k4_direct<<<dim3(17, B_), 256>>>(swf, scores, stats, senti, (float*)d_out);
}

// round 14
// speedup vs baseline: 1.1181x; 1.1181x over previous
#include <cuda_runtime.h>
#include <cstdint>

// Shapes (fixed for this problem)
#define B_   64
#define N_   2048
#define A_   512
#define RNN_ 1024
#define DW_  1024
#define DS_  1024
#define NCHUNK 16
#define NPER   (N_ / NCHUNK)   // 128

// k1 split-K GEMM config
#define KSPLIT 16
#define KCH    (RNN_ / KSPLIT)   // 64

// Scratch (device globals: no allocation allowed)
__device__ float g_pk1[KSPLIT * B_ * A_];       // 2 MB   (k1 partials)
__device__ float g_hword[B_ * A_];              // 128 KB
__device__ float g_scores[B_ * N_];             // 512 KB (raw scores)
__device__ float g_stats[2 * B_];               // [b]=max, [B_+b]=1/sum
__device__ float g_partial[B_ * NCHUNK * DW_];  // 4 MB

__device__ __forceinline__ float tanh_fast(float x) {
    float r;
    asm("tanh.approx.f32 %0, %1;" : "=f"(r) : "f"(x));
    return r;
}

__device__ __forceinline__ float warp_sum(float v) {
    #pragma unroll
    for (int o = 16; o; o >>= 1) v += __shfl_xor_sync(0xffffffffu, v, o);
    return v;
}

// PDL wait: with NO explicit trigger in the primary, programmatic completion
// fires at primary-kernel COMPLETION, so this is a full data-ready wait.
__device__ __forceinline__ void pdl_wait() {
#if __CUDA_ARCH__ >= 900
    cudaGridDependencySynchronize();
#endif
}

// ---------------------------------------------------------------------------
// K1: split-K tiled GEMM. pk1[ks][b][a] = sum_{k in chunk ks} h[b,k] * W[a,k]
// grid = (16, 16), block = 256.  (R3/R10-measured, unchanged; NO trigger)
// ---------------------------------------------------------------------------
__global__ void k1_gemm(const float* __restrict__ h,
                        const float* __restrict__ W,
                        float* __restrict__ pk1) {
    const int a0 = blockIdx.x * 32;
    const int k0 = blockIdx.y * KCH;

    __shared__ float sH[64][KCH + 4];
    __shared__ float sW[32][KCH + 4];

    for (int idx = threadIdx.x; idx < 64 * (KCH / 4); idx += 256) {
        const int row = idx >> 4, kk = idx & 15;
        float4 v = *(const float4*)(h + (size_t)row * RNN_ + k0 + kk * 4);
        *(float4*)(&sH[row][kk * 4]) = v;
    }
    for (int idx = threadIdx.x; idx < 32 * (KCH / 4); idx += 256) {
        const int row = idx >> 4, kk = idx & 15;
        float4 v = *(const float4*)(W + (size_t)(a0 + row) * RNN_ + k0 + kk * 4);
        *(float4*)(&sW[row][kk * 4]) = v;
    }
    __syncthreads();

    const int b  = threadIdx.x & 63;
    const int ag = threadIdx.x >> 6;

    float acc[8] = {0.f, 0.f, 0.f, 0.f, 0.f, 0.f, 0.f, 0.f};
    #pragma unroll 8
    for (int k4 = 0; k4 < KCH / 4; k4++) {
        const float4 hv = *(const float4*)(&sH[b][k4 * 4]);
        #pragma unroll
        for (int j = 0; j < 8; j++) {
            const float4 wv = *(const float4*)(&sW[ag * 8 + j][k4 * 4]);
            acc[j] += hv.x * wv.x + hv.y * wv.y + hv.z * wv.z + hv.w * wv.w;
        }
    }

    float* dst = pk1 + ((size_t)blockIdx.y * B_ + b) * A_ + a0 + ag * 8;
    #pragma unroll
    for (int j = 0; j < 8; j++) dst[j] = acc[j];
}

// ---------------------------------------------------------------------------
// K1r: hw[b][a] = bias[a] + sum_ks pk1[ks][b][a].
// ---------------------------------------------------------------------------
__global__ void k1_reduce(const float* __restrict__ pk1,
                          const float* __restrict__ bias,
                          float* __restrict__ hw) {
    const int idx = blockIdx.x * 256 + threadIdx.x;
    const int c = idx & 127;
    const int b = idx >> 7;
    pdl_wait();                       // k1_gemm fully complete -> pk1 ready
    float4 acc = ((const float4*)bias)[c];
    #pragma unroll
    for (int ks = 0; ks < KSPLIT; ks++) {
        float4 v = ((const float4*)pk1)[((size_t)ks * B_ + b) * (A_ / 4) + c];
        acc.x += v.x; acc.y += v.y; acc.z += v.z; acc.w += v.w;
    }
    ((float4*)hw)[idx] = acc;
}

// ---------------------------------------------------------------------------
// K2: scores[b,n] = sum_a tanh(p[b,n,a] + hw[b,a]) * walpha[a]
// grid = (N_/32, B_), block = 256.  EXACT R3/R10-measured body.
// ---------------------------------------------------------------------------
__global__ void k2_scores(const float* __restrict__ p,
                          const float* __restrict__ hw,
                          const float* __restrict__ walpha,
                          float* __restrict__ scores) {
    const int b = blockIdx.y;
    const int warp = threadIdx.x >> 5, lane = threadIdx.x & 31;
    const int n0 = blockIdx.x * 32 + warp * 4;
    pdl_wait();                       // k1_reduce complete -> hw ready

    float4 hv[4], wv[4];
    #pragma unroll
    for (int i = 0; i < 4; i++) {
        hv[i] = __ldg((const float4*)(hw + (size_t)b * A_) + lane + 32 * i);
        wv[i] = __ldg((const float4*)walpha + lane + 32 * i);
    }

    #pragma unroll
    for (int nn = 0; nn < 4; nn++) {
        const float4* pr = (const float4*)(p + ((size_t)b * N_ + n0 + nn) * A_);
        float4 v0 = __ldcs(pr + lane);
        float4 v1 = __ldcs(pr + lane + 32);
        float4 v2 = __ldcs(pr + lane + 64);
        float4 v3 = __ldcs(pr + lane + 96);

        float acc;
        acc  = tanh_fast(v0.x + hv[0].x) * wv[0].x;
        acc += tanh_fast(v0.y + hv[0].y) * wv[0].y;
        acc += tanh_fast(v0.z + hv[0].z) * wv[0].z;
        acc += tanh_fast(v0.w + hv[0].w) * wv[0].w;
        acc += tanh_fast(v1.x + hv[1].x) * wv[1].x;
        acc += tanh_fast(v1.y + hv[1].y) * wv[1].y;
        acc += tanh_fast(v1.z + hv[1].z) * wv[1].z;
        acc += tanh_fast(v1.w + hv[1].w) * wv[1].w;
        acc += tanh_fast(v2.x + hv[2].x) * wv[2].x;
        acc += tanh_fast(v2.y + hv[2].y) * wv[2].y;
        acc += tanh_fast(v2.z + hv[2].z) * wv[2].z;
        acc += tanh_fast(v2.w + hv[2].w) * wv[2].w;
        acc += tanh_fast(v3.x + hv[3].x) * wv[3].x;
        acc += tanh_fast(v3.y + hv[3].y) * wv[3].y;
        acc += tanh_fast(v3.z + hv[3].z) * wv[3].z;
        acc += tanh_fast(v3.w + hv[3].w) * wv[3].w;

        acc = warp_sum(acc);
        if (lane == 0) scores[(size_t)b * N_ + n0 + nn] = acc;
    }
}

// ---------------------------------------------------------------------------
// K3: stats-only softmax: stats[b]=max, stats[B_+b]=1/sum(exp(s-m)).
// grid = B_, block = 256.  (R10-measured)
// ---------------------------------------------------------------------------
__global__ void k3_stats(const float* __restrict__ scores,
                         float* __restrict__ stats) {
    const int b = blockIdx.x;
    const int t = threadIdx.x;
    const int warp = t >> 5, lane = t & 31;
    __shared__ float red[8];

    pdl_wait();                       // k2 complete -> scores ready
    const float* srow = scores + (size_t)b * N_;
    const float4 s0 = __ldg((const float4*)srow + 2 * t);
    const float4 s1 = __ldg((const float4*)srow + 2 * t + 1);

    float m = fmaxf(fmaxf(fmaxf(s0.x, s0.y), fmaxf(s0.z, s0.w)),
                    fmaxf(fmaxf(s1.x, s1.y), fmaxf(s1.z, s1.w)));
    #pragma unroll
    for (int o = 16; o; o >>= 1) m = fmaxf(m, __shfl_xor_sync(0xffffffffu, m, o));
    if (lane == 0) red[warp] = m;
    __syncthreads();
    float mm = red[0];
    #pragma unroll
    for (int j = 1; j < 8; j++) mm = fmaxf(mm, red[j]);
    __syncthreads();

    float sum = __expf(s0.x - mm) + __expf(s0.y - mm) +
                __expf(s0.z - mm) + __expf(s0.w - mm) +
                __expf(s1.x - mm) + __expf(s1.y - mm) +
                __expf(s1.z - mm) + __expf(s1.w - mm);
    sum = warp_sum(sum);
    if (lane == 0) red[warp] = sum;
    __syncthreads();
    if (t == 0) {
        float tot = red[0];
        #pragma unroll
        for (int j = 1; j < 8; j++) tot += red[j];
        stats[b] = mm;
        stats[B_ + b] = 1.0f / tot;
    }
}

// ---------------------------------------------------------------------------
// K4: partial[b,c,d] = sum_{n in chunk c} w[b,n] * swf[b,n,d]
// grid = (NCHUNK, B_), block = 256.  EXACT R7/R10-measured body
// (80.5us, 84.8% DRAM, 32 regs) — only a PDL wait at entry.
// ---------------------------------------------------------------------------
__global__ void k4_pool(const float* __restrict__ swf,
                        const float* __restrict__ scores,
                        const float* __restrict__ stats,
                        float* __restrict__ partial) {
    pdl_wait();                       // k3 complete -> scores + stats ready
    const int b = blockIdx.y, c = blockIdx.x;
    __shared__ float sw[NPER];
    if (threadIdx.x < NPER) {
        const float m   = __ldg(stats + b);
        const float inv = __ldg(stats + B_ + b);
        sw[threadIdx.x] =
            __expf(__ldg(scores + (size_t)b * N_ + c * NPER + threadIdx.x) - m) * inv;
    }
    __syncthreads();

    const float4* x = (const float4*)(swf + ((size_t)b * N_ + (size_t)c * NPER) * DW_);
    const int t = threadIdx.x;
    float4 acc = make_float4(0.f, 0.f, 0.f, 0.f);
    #pragma unroll 8
    for (int n = 0; n < NPER; n++) {
        const float wn = sw[n];
        const float4 v = __ldcs(x + (size_t)n * (DW_ / 4) + t);
        acc.x += wn * v.x; acc.y += wn * v.y;
        acc.z += wn * v.z; acc.w += wn * v.w;
    }
    ((float4*)partial)[((size_t)b * NCHUNK + c) * (DW_ / 4) + t] = acc;
}

// ---------------------------------------------------------------------------
// K5: out[b] = concat(senti_feats[b], sum_c partial[b,c,:]). grid = B_, 256.
// senti copy is predecessor-independent: done BEFORE the PDL wait, so it
// overlaps k4's tail.
// ---------------------------------------------------------------------------
__global__ void k5_finish(const float* __restrict__ senti,
                          const float* __restrict__ partial,
                          float* __restrict__ out) {
    const int b = blockIdx.x, t = threadIdx.x;
    float4* orow = (float4*)(out + (size_t)b * (DS_ + DW_));
    orow[t] = ((const float4*)(senti + (size_t)b * DS_))[t];   // independent
    pdl_wait();                       // k4 complete -> partial ready
    float4 acc = make_float4(0.f, 0.f, 0.f, 0.f);
    #pragma unroll
    for (int c = 0; c < NCHUNK; c++) {
        float4 v = __ldg(((const float4*)partial) + ((size_t)b * NCHUNK + c) * (DW_ / 4) + t);
        acc.x += v.x; acc.y += v.y; acc.z += v.z; acc.w += v.w;
    }
    orow[DS_ / 4 + t] = acc;
}

// ---------------------------------------------------------------------------
// Launch helper: PDL-enabled launch (programmatic stream serialization)
// ---------------------------------------------------------------------------
template <typename K, typename... Args>
static inline void launch_pdl(K kernel, dim3 grid, dim3 block, Args... args) {
    cudaLaunchConfig_t cfg = {};
    cfg.gridDim = grid;
    cfg.blockDim = block;
    cudaLaunchAttribute attr;
    attr.id = cudaLaunchAttributeProgrammaticStreamSerialization;
    attr.val.programmaticStreamSerializationAllowed = 1;
    cfg.attrs = &attr;
    cfg.numAttrs = 1;
    cudaLaunchKernelEx(&cfg, kernel, args...);
}

// ---------------------------------------------------------------------------
extern "C" void kernel_launch(void* const* d_in, const int* in_sizes, int n_in,
                              void* d_out, int out_size) {
    const float* h      = (const float*)d_in[0];  // [B, RNN]
    const float* senti  = (const float*)d_in[1];  // [B, DS]
    const float* swf    = (const float*)d_in[2];  // [B, N, DW]
    const float* p      = (const float*)d_in[3];  // [B, N, A]
    const float* W      = (const float*)d_in[4];  // [A, RNN]
    const float* bvec   = (const float*)d_in[5];  // [A]
    const float* walpha = (const float*)d_in[6];  // [A]
    // d_in[7] = b_alpha: softmax-invariant, ignored.

    float* pk1;     cudaGetSymbolAddress((void**)&pk1,     g_pk1);
    float* hw;      cudaGetSymbolAddress((void**)&hw,      g_hword);
    float* scores;  cudaGetSymbolAddress((void**)&scores,  g_scores);
    float* stats;   cudaGetSymbolAddress((void**)&stats,   g_stats);
    float* partial; cudaGetSymbolAddress((void**)&partial, g_partial);

    k1_gemm<<<dim3(A_ / 32, KSPLIT), 256>>>(h, W, pk1);
    launch_pdl(k1_reduce, dim3((B_ * A_ / 4) / 256), dim3(256), pk1, (const float*)bvec, hw);
    launch_pdl(k2_scores, dim3(N_ / 32, B_), dim3(256), p, (const float*)hw, walpha, scores);
    launch_pdl(k3_stats,  dim3(B_), dim3(256), (const float*)scores, stats);
    launch_pdl(k4_pool,   dim3(NCHUNK, B_), dim3(256), swf, (const float*)scores,
               (const float*)stats, partial);
    launch_pdl(k5_finish, dim3(B_), dim3(256), senti, (const float*)partial, (float*)d_out);
}